// round 6
// baseline (speedup 1.0000x reference)
#include <cuda_runtime.h>
#include <cstdint>

#define N_TOK 4096
#define DDIM  1024
#define BK 16
#define BM 256
#define BN 128

// Scratch (device globals; no runtime allocation)
__device__ float g_Q[(size_t)N_TOK * DDIM];
__device__ float g_K[(size_t)N_TOK * DDIM];
__device__ float g_V[(size_t)N_TOK * DDIM];
__device__ float g_Vt[(size_t)DDIM * N_TOK];       // V transposed [dim][token]
__device__ float g_Wt[3][(size_t)DDIM * DDIM];     // W transposed [out][in]
__device__ float g_P[(size_t)N_TOK * N_TOK];
__device__ float g_rsum[N_TOK];

// Pair-packed smem, XOR swizzle. Byte offsets within one stage:
//  A: 2 k-planes x (256 rows x 4 pairs x 8B) = 2 x 8192
//  B: at 16384: 2 k-planes x (128 rows x 4 pairs x 8B) = 2 x 4096
// Pair (row, slot s) of plane h holds tf32 cols (t, t+4) of k-half h, t = s ^ ((row>>2)&3).
#define B_OFF   16384
#define STAGE_B 24576

__device__ __forceinline__ uint32_t f2tf32(float x) {
    uint32_t u;
    asm volatile("cvt.rna.tf32.f32 %0, %1;" : "=r"(u) : "f"(x));
    return u;
}

__device__ __forceinline__ void mma_tf32(float d[4], uint32_t a0, uint32_t a1, uint32_t a2,
                                         uint32_t a3, uint32_t b0, uint32_t b1) {
    asm volatile(
        "mma.sync.aligned.m16n8k8.row.col.f32.tf32.tf32.f32 "
        "{%0,%1,%2,%3}, {%4,%5,%6,%7}, {%8,%9}, {%0,%1,%2,%3};\n"
        : "+f"(d[0]), "+f"(d[1]), "+f"(d[2]), "+f"(d[3])
        : "r"(a0), "r"(a1), "r"(a2), "r"(a3), "r"(b0), "r"(b1));
}

// global -> regs: A row tid (16 floats), B row tid>>1 half tid&1 (8 floats)
__device__ __forceinline__ void global_load(
    const float* __restrict__ A, const float* __restrict__ B,
    int lda, int ldb, int bm, int bn, int kt, int tid,
    float4 ra[4], float4 rb[2])
{
    const float* pa = A + (size_t)(bm + tid) * lda + kt * BK;
    ra[0] = *reinterpret_cast<const float4*>(pa);
    ra[1] = *reinterpret_cast<const float4*>(pa + 4);
    ra[2] = *reinterpret_cast<const float4*>(pa + 8);
    ra[3] = *reinterpret_cast<const float4*>(pa + 12);
    const float* pb = B + (size_t)(bn + (tid >> 1)) * ldb + kt * BK + (tid & 1) * 8;
    rb[0] = *reinterpret_cast<const float4*>(pb);
    rb[1] = *reinterpret_cast<const float4*>(pb + 4);
}

// regs -> smem (tf32, XOR swizzle). 8 + 4 STS.64 per thread, 2-way max.
__device__ __forceinline__ void smem_store(char* stage, int tid,
                                           const float4 ra[4], const float4 rb[2])
{
    const int rowA = tid;
    const uint32_t vA = (rowA >> 2) & 3;
    char* pa = stage + rowA * 32;
#pragma unroll
    for (int h = 0; h < 2; h++) {
        const float* f = reinterpret_cast<const float*>(&ra[2 * h]);  // 8 floats
#pragma unroll
        for (int c = 0; c < 4; c++)
            *reinterpret_cast<uint2*>(pa + h * 8192 + 8 * (c ^ vA)) =
                make_uint2(f2tf32(f[c]), f2tf32(f[c + 4]));
    }
    const int rowB = tid >> 1, hB = tid & 1;
    const uint32_t vB = (rowB >> 2) & 3;
    char* pb = stage + B_OFF + hB * 4096 + rowB * 32;
    const float* g = reinterpret_cast<const float*>(&rb[0]);
#pragma unroll
    for (int c = 0; c < 4; c++)
        *reinterpret_cast<uint2*>(pb + 8 * (c ^ vB)) =
            make_uint2(f2tf32(g[c]), f2tf32(g[c + 4]));
}

// CTA tile 256x128, 8 warps as 4(M) x 2(N), warp tile 64x64, double-buffered.
// A [M x K] row-major, B [N x K] row-major.
__device__ __forceinline__ void gemm_main(
    const float* __restrict__ A, const float* __restrict__ B,
    int lda, int ldb, int kIters, int bm, int bn,
    char* smem, float (&acc)[4][8][4])
{
    const int tid = threadIdx.x;

#pragma unroll
    for (int mi = 0; mi < 4; mi++)
#pragma unroll
        for (int ni = 0; ni < 8; ni++)
#pragma unroll
            for (int j = 0; j < 4; j++) acc[mi][ni][j] = 0.f;

    float4 ra[4], rb[2];
    global_load(A, B, lda, ldb, bm, bn, 0, tid, ra, rb);
    smem_store(smem, tid, ra, rb);
    __syncthreads();

    const int w = tid >> 5, lane = tid & 31;
    const int wm = (w & 3) * 64;        // M quadrant (rows wm..wm+63)
    const int wn = (w >> 2) * 64;       // N half (cols wn..wn+63)
    const int gid = lane >> 2, tig = lane & 3;
    const uint32_t sl = (uint32_t)(tig ^ (gid >> 2));     // base slot
    // A lane bases (byte offsets in stage)
    const uint32_t aLo = (uint32_t)((wm + gid) * 32) + 8 * sl;
    const uint32_t aHi = aLo ^ 16;      // +8 rows handled by +256; slot^2 == byte^16
    // B lane bases
    const uint32_t bLo = (uint32_t)(B_OFF + (wn + gid) * 32) + 8 * sl;
    const uint32_t bHi = bLo ^ 16;      // odd ni: slot^2

    for (int kt = 0; kt < kIters; ++kt) {
        if (kt + 1 < kIters)
            global_load(A, B, lda, ldb, bm, bn, kt + 1, tid, ra, rb);

        const char* sbuf = smem + (kt & 1) * STAGE_B;

#pragma unroll
        for (int ks = 0; ks < 2; ks++) {
            uint2 alo[4], ahi[4], bb[8];
#pragma unroll
            for (int mi = 0; mi < 4; mi++) {
                alo[mi] = *reinterpret_cast<const uint2*>(sbuf + aLo + ks * 8192 + mi * 512);
                ahi[mi] = *reinterpret_cast<const uint2*>(sbuf + aHi + ks * 8192 + mi * 512 + 256);
            }
#pragma unroll
            for (int ni = 0; ni < 8; ni++) {
                uint32_t base = (ni & 1) ? bHi : bLo;
                bb[ni] = *reinterpret_cast<const uint2*>(sbuf + base + ks * 4096 + ni * 256);
            }
#pragma unroll
            for (int mi = 0; mi < 4; mi++)
#pragma unroll
                for (int ni = 0; ni < 8; ni++)
                    mma_tf32(acc[mi][ni], alo[mi].x, ahi[mi].x, alo[mi].y, ahi[mi].y,
                             bb[ni].x, bb[ni].y);
        }

        if (kt + 1 < kIters)
            smem_store(smem + ((kt + 1) & 1) * STAGE_B, tid, ra, rb);
        __syncthreads();
    }
}

// ---------- transpose: out[c][r] = in[r][c]; out selected by index ----------
__global__ void __launch_bounds__(256)
transpose_kernel(const float* __restrict__ in, int out_idx, int rows, int cols)
{
    __shared__ float t[32][33];
    const float* src = (out_idx == 3) ? g_V : in;
    float* dst = (out_idx == 3) ? g_Vt : g_Wt[out_idx];
    const int bx = blockIdx.x * 32, by = blockIdx.y * 32;
    const int tx = threadIdx.x & 31, ty = threadIdx.x >> 5;  // 32 x 8
#pragma unroll
    for (int i = 0; i < 32; i += 8)
        t[ty + i][tx] = src[(size_t)(by + ty + i) * cols + bx + tx];
    __syncthreads();
#pragma unroll
    for (int i = 0; i < 32; i += 8)
        dst[(size_t)(bx + ty + i) * rows + by + tx] = t[tx][ty + i];
}

// ---------- Kernel 1: Q/K/V = X @ W + b ----------
__global__ void __launch_bounds__(256, 1)
qkv_kernel(const float* __restrict__ x,
           const float* __restrict__ bq, const float* __restrict__ bk,
           const float* __restrict__ bv)
{
    __shared__ __align__(16) char smem[2 * STAGE_B];
    const float* bias; float* O;
    if (blockIdx.z == 0)      { bias = bq; O = g_Q; }
    else if (blockIdx.z == 1) { bias = bk; O = g_K; }
    else                      { bias = bv; O = g_V; }
    const float* W = g_Wt[blockIdx.z];

    const int bm = blockIdx.y * BM, bn = blockIdx.x * BN;
    float acc[4][8][4];
    gemm_main(x, W, DDIM, DDIM, DDIM / BK, bm, bn, smem, acc);

    const int w = threadIdx.x >> 5, lane = threadIdx.x & 31;
    const int wm = (w & 3) * 64, wn = (w >> 2) * 64;
    const int gid = lane >> 2, tig = lane & 3;
#pragma unroll
    for (int mi = 0; mi < 4; mi++) {
        int r0 = bm + wm + mi * 16 + gid;
#pragma unroll
        for (int ni = 0; ni < 8; ni++) {
            int c = bn + wn + ni * 8 + 2 * tig;
            float b0 = bias[c], b1 = bias[c + 1];
            float2 v0 = make_float2(acc[mi][ni][0] + b0, acc[mi][ni][1] + b1);
            float2 v1 = make_float2(acc[mi][ni][2] + b0, acc[mi][ni][3] + b1);
            *reinterpret_cast<float2*>(&O[(size_t)r0 * DDIM + c]) = v0;
            *reinterpret_cast<float2*>(&O[(size_t)(r0 + 8) * DDIM + c]) = v1;
        }
    }
}

// ---------- Kernel 2: P = exp(tanh(Q @ K^T) / 32) ----------
__global__ void __launch_bounds__(256, 1)
score_kernel()
{
    __shared__ __align__(16) char smem[2 * STAGE_B];
    const int bm = blockIdx.y * BM, bn = blockIdx.x * BN;
    float acc[4][8][4];
    gemm_main(g_Q, g_K, DDIM, DDIM, DDIM / BK, bm, bn, smem, acc);

    const int w = threadIdx.x >> 5, lane = threadIdx.x & 31;
    const int wm = (w & 3) * 64, wn = (w >> 2) * 64;
    const int gid = lane >> 2, tig = lane & 3;
    const float sc = 0.03125f;  // 1/sqrt(1024)
#pragma unroll
    for (int mi = 0; mi < 4; mi++) {
        int r0 = bm + wm + mi * 16 + gid;
#pragma unroll
        for (int ni = 0; ni < 8; ni++) {
            int c = bn + wn + ni * 8 + 2 * tig;
            float e[4];
#pragma unroll
            for (int q = 0; q < 4; q++) {
                float t;
                asm("tanh.approx.f32 %0, %1;" : "=f"(t) : "f"(acc[mi][ni][q]));
                e[q] = __expf(t * sc);
            }
            *reinterpret_cast<float2*>(&g_P[(size_t)r0 * N_TOK + c]) = make_float2(e[0], e[1]);
            *reinterpret_cast<float2*>(&g_P[(size_t)(r0 + 8) * N_TOK + c]) = make_float2(e[2], e[3]);
        }
    }
}

// ---------- Kernel 3: row sums of P ----------
__global__ void __launch_bounds__(256)
rowsum_kernel()
{
    const int row = blockIdx.x;
    const float4* p = reinterpret_cast<const float4*>(g_P + (size_t)row * N_TOK);
    float s = 0.f;
#pragma unroll
    for (int i = 0; i < 4; i++) {
        float4 v = p[threadIdx.x + i * 256];
        s += (v.x + v.y) + (v.z + v.w);
    }
#pragma unroll
    for (int o = 16; o > 0; o >>= 1) s += __shfl_xor_sync(0xffffffffu, s, o);
    __shared__ float red[8];
    if ((threadIdx.x & 31) == 0) red[threadIdx.x >> 5] = s;
    __syncthreads();
    if (threadIdx.x < 8) {
        float t = red[threadIdx.x];
#pragma unroll
        for (int o = 4; o > 0; o >>= 1) t += __shfl_xor_sync(0xffu, t, o);
        if (threadIdx.x == 0) g_rsum[row] = t;
    }
}

// ---------- Kernel 4: out = (P @ V) / rsum ----------
__global__ void __launch_bounds__(256, 1)
pv_kernel(float* __restrict__ out)
{
    __shared__ __align__(16) char smem[2 * STAGE_B];
    const int bm = blockIdx.y * BM, bn = blockIdx.x * BN;
    float acc[4][8][4];
    gemm_main(g_P, g_Vt, N_TOK, N_TOK, N_TOK / BK, bm, bn, smem, acc);

    const int w = threadIdx.x >> 5, lane = threadIdx.x & 31;
    const int wm = (w & 3) * 64, wn = (w >> 2) * 64;
    const int gid = lane >> 2, tig = lane & 3;
#pragma unroll
    for (int mi = 0; mi < 4; mi++) {
        int r0 = bm + wm + mi * 16 + gid;
        float inv0 = 1.0f / g_rsum[r0];
        float inv1 = 1.0f / g_rsum[r0 + 8];
#pragma unroll
        for (int ni = 0; ni < 8; ni++) {
            int c = bn + wn + ni * 8 + 2 * tig;
            float2 v0 = make_float2(acc[mi][ni][0] * inv0, acc[mi][ni][1] * inv0);
            float2 v1 = make_float2(acc[mi][ni][2] * inv1, acc[mi][ni][3] * inv1);
            *reinterpret_cast<float2*>(&out[(size_t)r0 * DDIM + c]) = v0;
            *reinterpret_cast<float2*>(&out[(size_t)(r0 + 8) * DDIM + c]) = v1;
        }
    }
}

extern "C" void kernel_launch(void* const* d_in, const int* in_sizes, int n_in,
                              void* d_out, int out_size)
{
    const float* x  = (const float*)d_in[0];
    const float* Wq = (const float*)d_in[1];
    const float* bq = (const float*)d_in[2];
    const float* Wk = (const float*)d_in[3];
    const float* bk = (const float*)d_in[4];
    const float* Wv = (const float*)d_in[5];
    const float* bv = (const float*)d_in[6];
    float* out = (float*)d_out;

    transpose_kernel<<<dim3(32, 32), 256>>>(Wq, 0, DDIM, DDIM);
    transpose_kernel<<<dim3(32, 32), 256>>>(Wk, 1, DDIM, DDIM);
    transpose_kernel<<<dim3(32, 32), 256>>>(Wv, 2, DDIM, DDIM);
    qkv_kernel<<<dim3(DDIM / BN, N_TOK / BM, 3), 256>>>(x, bq, bk, bv);
    transpose_kernel<<<dim3(DDIM / 32, N_TOK / 32), 256>>>(nullptr, 3, N_TOK, DDIM);
    score_kernel<<<dim3(N_TOK / BN, N_TOK / BM), 256>>>();
    rowsum_kernel<<<N_TOK, 256>>>();
    pv_kernel<<<dim3(DDIM / BN, N_TOK / BM), 256>>>(out);
}

// round 7
// speedup vs baseline: 2.6743x; 2.6743x over previous
#include <cuda_runtime.h>
#include <cuda_fp16.h>
#include <cstdint>

#define N_TOK 4096
#define DDIM  1024
#define BK 32            // halves per k-chunk (2 planes of k16)
#define STAGE_B 16384    // A 8KB (2 planes x 4KB) + B 8KB at offset 8192

// Scratch (device globals; no runtime allocation)
__device__ __half g_Xh[(size_t)N_TOK * DDIM];
__device__ __half g_Q[(size_t)N_TOK * DDIM];
__device__ __half g_K[(size_t)N_TOK * DDIM];
__device__ __half g_V[(size_t)N_TOK * DDIM];
__device__ __half g_Vt[(size_t)DDIM * N_TOK];     // V^T [dim][token]
__device__ __half g_Wt[3][(size_t)DDIM * DDIM];   // W^T [out][in]
__device__ __half g_P[(size_t)N_TOK * N_TOK];
__device__ float  g_rsum[N_TOK];

// Smem layout per stage (bytes): plane h (k16 step) of A at h*4096, of B at 8192+h*4096.
// Row r holds 8 half2 "units" (kpairs 0..7) as 4 pairs; pair m = (unit m, unit m+4),
// stored at r*32 + 8*((m + ((r>>2)&3) + 2h) & 3), words (unit m at +0, unit m+4 at +4).
// Verified conflict-free for STS.32 scatter and LDS.64 fragment loads.

__device__ __forceinline__ void mma_f16(float d[4], uint32_t a0, uint32_t a1, uint32_t a2,
                                        uint32_t a3, uint32_t b0, uint32_t b1) {
    asm volatile(
        "mma.sync.aligned.m16n8k16.row.col.f32.f16.f16.f32 "
        "{%0,%1,%2,%3}, {%4,%5,%6,%7}, {%8,%9}, {%0,%1,%2,%3};\n"
        : "+f"(d[0]), "+f"(d[1]), "+f"(d[2]), "+f"(d[3])
        : "r"(a0), "r"(a1), "r"(a2), "r"(a3), "r"(b0), "r"(b1));
}

// Coalesced global load: thread (r0 = tid>>2, chunk q = tid&3) reads 16B of rows
// r0 + 32*i for i in 0..3, for both A and B. Warp covers 512B contiguous per instr.
__device__ __forceinline__ void global_load(
    const __half* __restrict__ A, const __half* __restrict__ B,
    int lda, int ldb, int bm, int bn, int kt, int tid,
    uint4 ra[4], uint4 rb[4])
{
    const int r0 = tid >> 2, q = tid & 3;
    const __half* pa = A + (size_t)(bm + r0) * lda + kt * BK + q * 8;
    const __half* pb = B + (size_t)(bn + r0) * ldb + kt * BK + q * 8;
#pragma unroll
    for (int i = 0; i < 4; i++) {
        ra[i] = *reinterpret_cast<const uint4*>(pa + (size_t)(32 * i) * lda);
        rb[i] = *reinterpret_cast<const uint4*>(pb + (size_t)(32 * i) * ldb);
    }
}

// Scatter store: thread's 16B chunk = units 4q..4q+3 -> plane h=q>>1, word w=q&1 of
// pairs m=0..3. 32 STS.32 per thread per kt, conflict-free.
__device__ __forceinline__ void smem_store(char* stage, int tid,
                                           const uint4 ra[4], const uint4 rb[4])
{
    const int r0 = tid >> 2, q = tid & 3;
    const int h = q >> 1;
    const int v = (r0 >> 2) & 3;
    const int o0 = 8 * ((0 + v + 2 * h) & 3), o1 = 8 * ((1 + v + 2 * h) & 3);
    const int o2 = 8 * ((2 + v + 2 * h) & 3), o3 = 8 * ((3 + v + 2 * h) & 3);
    char* pa = stage + h * 4096 + r0 * 32 + 4 * (q & 1);
    char* pb = pa + 8192;
#pragma unroll
    for (int i = 0; i < 4; i++) {
        char* p = pa + i * 1024;
        *reinterpret_cast<uint32_t*>(p + o0) = ra[i].x;
        *reinterpret_cast<uint32_t*>(p + o1) = ra[i].y;
        *reinterpret_cast<uint32_t*>(p + o2) = ra[i].z;
        *reinterpret_cast<uint32_t*>(p + o3) = ra[i].w;
        char* s = pb + i * 1024;
        *reinterpret_cast<uint32_t*>(s + o0) = rb[i].x;
        *reinterpret_cast<uint32_t*>(s + o1) = rb[i].y;
        *reinterpret_cast<uint32_t*>(s + o2) = rb[i].z;
        *reinterpret_cast<uint32_t*>(s + o3) = rb[i].w;
    }
}

__device__ __forceinline__ int swz(int r, int t, int h) {
    return r * 32 + 8 * ((t + ((r >> 2) & 3) + 2 * h) & 3);
}

// CTA 128x128, 4 warps as 2(M) x 2(N), warp tile 64x64, double-buffered, fp16 inputs.
// A [M x K] half row-major, B [N x K] half row-major, fp32 accum.
__device__ __forceinline__ void gemm_main(
    const __half* __restrict__ A, const __half* __restrict__ B,
    int lda, int ldb, int kIters, int bm, int bn,
    char* smem, float (&acc)[4][8][4])
{
    const int tid = threadIdx.x;

#pragma unroll
    for (int mi = 0; mi < 4; mi++)
#pragma unroll
        for (int ni = 0; ni < 8; ni++)
#pragma unroll
            for (int j = 0; j < 4; j++) acc[mi][ni][j] = 0.f;

    uint4 ra[4], rb[4];
    global_load(A, B, lda, ldb, bm, bn, 0, tid, ra, rb);
    smem_store(smem, tid, ra, rb);
    __syncthreads();

    const int w = tid >> 5, lane = tid & 31;
    const int wm = (w & 1) * 64, wn = (w >> 1) * 64;
    const int gid = lane >> 2, tig = lane & 3;
    uint32_t aL[2], aH[2], bE[2], bO[2];
#pragma unroll
    for (int h = 0; h < 2; h++) {
        aL[h] = h * 4096 + swz(wm + gid, tig, h);
        aH[h] = h * 4096 + swz(wm + gid + 8, tig, h);
        bE[h] = 8192 + h * 4096 + swz(wn + gid, tig, h);
        bO[h] = 8192 + h * 4096 + swz(wn + gid + 8, tig, h);
    }

    for (int kt = 0; kt < kIters; ++kt) {
        if (kt + 1 < kIters)
            global_load(A, B, lda, ldb, bm, bn, kt + 1, tid, ra, rb);

        const char* sbuf = smem + (kt & 1) * STAGE_B;

#pragma unroll
        for (int h = 0; h < 2; h++) {
            uint2 alo[4], ahi[4], bb[8];
#pragma unroll
            for (int mi = 0; mi < 4; mi++) {
                alo[mi] = *reinterpret_cast<const uint2*>(sbuf + aL[h] + mi * 512);
                ahi[mi] = *reinterpret_cast<const uint2*>(sbuf + aH[h] + mi * 512);
            }
#pragma unroll
            for (int ni = 0; ni < 8; ni++)
                bb[ni] = *reinterpret_cast<const uint2*>(
                    sbuf + (ni & 1 ? bO[h] : bE[h]) + (ni >> 1) * 512);
#pragma unroll
            for (int mi = 0; mi < 4; mi++)
#pragma unroll
                for (int ni = 0; ni < 8; ni++)
                    mma_f16(acc[mi][ni], alo[mi].x, ahi[mi].x, alo[mi].y, ahi[mi].y,
                            bb[ni].x, bb[ni].y);
        }

        if (kt + 1 < kIters)
            smem_store(smem + ((kt + 1) & 1) * STAGE_B, tid, ra, rb);
        __syncthreads();
    }
}

// ---------- x -> half ----------
__global__ void __launch_bounds__(256)
convert_x_kernel(const float* __restrict__ x)
{
    const size_t base = ((size_t)blockIdx.x * 256 + threadIdx.x) * 8;
    float4 v0 = *reinterpret_cast<const float4*>(x + base);
    float4 v1 = *reinterpret_cast<const float4*>(x + base + 4);
    __half2* o = reinterpret_cast<__half2*>(g_Xh + base);
    o[0] = __floats2half2_rn(v0.x, v0.y);
    o[1] = __floats2half2_rn(v0.z, v0.w);
    o[2] = __floats2half2_rn(v1.x, v1.y);
    o[3] = __floats2half2_rn(v1.z, v1.w);
}

// ---------- W (fp32 [in][out]) -> Wt half [out][in] ----------
__global__ void __launch_bounds__(256)
transpose_w_kernel(const float* __restrict__ in, int idx)
{
    __shared__ float t[32][33];
    __half* dst = g_Wt[idx];
    const int bx = blockIdx.x * 32, by = blockIdx.y * 32;
    const int tx = threadIdx.x & 31, ty = threadIdx.x >> 5;
#pragma unroll
    for (int i = 0; i < 32; i += 8)
        t[ty + i][tx] = in[(size_t)(by + ty + i) * DDIM + bx + tx];
    __syncthreads();
#pragma unroll
    for (int i = 0; i < 32; i += 8)
        dst[(size_t)(bx + ty + i) * DDIM + by + tx] = __float2half(t[tx][ty + i]);
}

// ---------- V (half [tok][dim]) -> Vt half [dim][tok] ----------
__global__ void __launch_bounds__(256)
transpose_v_kernel()
{
    __shared__ float t[32][33];
    const int bx = blockIdx.x * 32, by = blockIdx.y * 32;
    const int tx = threadIdx.x & 31, ty = threadIdx.x >> 5;
#pragma unroll
    for (int i = 0; i < 32; i += 8)
        t[ty + i][tx] = __half2float(g_V[(size_t)(by + ty + i) * DDIM + bx + tx]);
    __syncthreads();
#pragma unroll
    for (int i = 0; i < 32; i += 8)
        g_Vt[(size_t)(bx + ty + i) * N_TOK + by + tx] = __float2half(t[tx][ty + i]);
}

// ---------- Kernel 1: Q/K/V = X @ W + b (half out) ----------
__global__ void __launch_bounds__(128, 2)
qkv_kernel(const float* __restrict__ bq, const float* __restrict__ bk,
           const float* __restrict__ bv)
{
    __shared__ __align__(16) char smem[2 * STAGE_B];
    const float* bias; __half* O;
    if (blockIdx.z == 0)      { bias = bq; O = g_Q; }
    else if (blockIdx.z == 1) { bias = bk; O = g_K; }
    else                      { bias = bv; O = g_V; }
    const __half* W = g_Wt[blockIdx.z];

    const int bm = blockIdx.y * 128, bn = blockIdx.x * 128;
    float acc[4][8][4];
    gemm_main(g_Xh, W, DDIM, DDIM, DDIM / BK, bm, bn, smem, acc);

    const int w = threadIdx.x >> 5, lane = threadIdx.x & 31;
    const int wm = (w & 1) * 64, wn = (w >> 1) * 64;
    const int gid = lane >> 2, tig = lane & 3;
#pragma unroll
    for (int mi = 0; mi < 4; mi++) {
        int r0 = bm + wm + mi * 16 + gid;
#pragma unroll
        for (int ni = 0; ni < 8; ni++) {
            int c = bn + wn + ni * 8 + 2 * tig;
            float b0 = bias[c], b1 = bias[c + 1];
            *reinterpret_cast<__half2*>(&O[(size_t)r0 * DDIM + c]) =
                __floats2half2_rn(acc[mi][ni][0] + b0, acc[mi][ni][1] + b1);
            *reinterpret_cast<__half2*>(&O[(size_t)(r0 + 8) * DDIM + c]) =
                __floats2half2_rn(acc[mi][ni][2] + b0, acc[mi][ni][3] + b1);
        }
    }
}

// ---------- Kernel 2: P = exp(tanh(Q @ K^T) / 32) (half out) ----------
__global__ void __launch_bounds__(128, 2)
score_kernel()
{
    __shared__ __align__(16) char smem[2 * STAGE_B];
    const int bm = blockIdx.y * 128, bn = blockIdx.x * 128;
    float acc[4][8][4];
    gemm_main(g_Q, g_K, DDIM, DDIM, DDIM / BK, bm, bn, smem, acc);

    const int w = threadIdx.x >> 5, lane = threadIdx.x & 31;
    const int wm = (w & 1) * 64, wn = (w >> 1) * 64;
    const int gid = lane >> 2, tig = lane & 3;
    const float sc = 0.03125f;  // 1/sqrt(1024)
#pragma unroll
    for (int mi = 0; mi < 4; mi++) {
        int r0 = bm + wm + mi * 16 + gid;
#pragma unroll
        for (int ni = 0; ni < 8; ni++) {
            int c = bn + wn + ni * 8 + 2 * tig;
            float e[4];
#pragma unroll
            for (int q = 0; q < 4; q++) {
                float t;
                asm("tanh.approx.f32 %0, %1;" : "=f"(t) : "f"(acc[mi][ni][q]));
                e[q] = __expf(t * sc);
            }
            *reinterpret_cast<__half2*>(&g_P[(size_t)r0 * N_TOK + c]) =
                __floats2half2_rn(e[0], e[1]);
            *reinterpret_cast<__half2*>(&g_P[(size_t)(r0 + 8) * N_TOK + c]) =
                __floats2half2_rn(e[2], e[3]);
        }
    }
}

// ---------- Kernel 3: row sums of P (half in, fp32 sum) ----------
__global__ void __launch_bounds__(256)
rowsum_kernel()
{
    const int row = blockIdx.x;
    const uint4* p = reinterpret_cast<const uint4*>(g_P + (size_t)row * N_TOK);
    float s = 0.f;
#pragma unroll
    for (int i = 0; i < 2; i++) {
        uint4 u = p[threadIdx.x + i * 256];
        float2 f0 = __half22float2(*reinterpret_cast<__half2*>(&u.x));
        float2 f1 = __half22float2(*reinterpret_cast<__half2*>(&u.y));
        float2 f2 = __half22float2(*reinterpret_cast<__half2*>(&u.z));
        float2 f3 = __half22float2(*reinterpret_cast<__half2*>(&u.w));
        s += (f0.x + f0.y) + (f1.x + f1.y) + (f2.x + f2.y) + (f3.x + f3.y);
    }
#pragma unroll
    for (int o = 16; o > 0; o >>= 1) s += __shfl_xor_sync(0xffffffffu, s, o);
    __shared__ float red[8];
    if ((threadIdx.x & 31) == 0) red[threadIdx.x >> 5] = s;
    __syncthreads();
    if (threadIdx.x < 8) {
        float t = red[threadIdx.x];
#pragma unroll
        for (int o = 4; o > 0; o >>= 1) t += __shfl_xor_sync(0xffu, t, o);
        if (threadIdx.x == 0) g_rsum[row] = t;
    }
}

// ---------- Kernel 4: out = (P @ V) / rsum (fp32 out) ----------
__global__ void __launch_bounds__(128, 2)
pv_kernel(float* __restrict__ out)
{
    __shared__ __align__(16) char smem[2 * STAGE_B];
    const int bm = blockIdx.y * 128, bn = blockIdx.x * 128;
    float acc[4][8][4];
    gemm_main(g_P, g_Vt, N_TOK, N_TOK, N_TOK / BK, bm, bn, smem, acc);

    const int w = threadIdx.x >> 5, lane = threadIdx.x & 31;
    const int wm = (w & 1) * 64, wn = (w >> 1) * 64;
    const int gid = lane >> 2, tig = lane & 3;
#pragma unroll
    for (int mi = 0; mi < 4; mi++) {
        int r0 = bm + wm + mi * 16 + gid;
        float inv0 = 1.0f / g_rsum[r0];
        float inv1 = 1.0f / g_rsum[r0 + 8];
#pragma unroll
        for (int ni = 0; ni < 8; ni++) {
            int c = bn + wn + ni * 8 + 2 * tig;
            float2 v0 = make_float2(acc[mi][ni][0] * inv0, acc[mi][ni][1] * inv0);
            float2 v1 = make_float2(acc[mi][ni][2] * inv1, acc[mi][ni][3] * inv1);
            *reinterpret_cast<float2*>(&out[(size_t)r0 * DDIM + c]) = v0;
            *reinterpret_cast<float2*>(&out[(size_t)(r0 + 8) * DDIM + c]) = v1;
        }
    }
}

extern "C" void kernel_launch(void* const* d_in, const int* in_sizes, int n_in,
                              void* d_out, int out_size)
{
    const float* x  = (const float*)d_in[0];
    const float* Wq = (const float*)d_in[1];
    const float* bq = (const float*)d_in[2];
    const float* Wk = (const float*)d_in[3];
    const float* bk = (const float*)d_in[4];
    const float* Wv = (const float*)d_in[5];
    const float* bv = (const float*)d_in[6];
    float* out = (float*)d_out;

    convert_x_kernel<<<(N_TOK * DDIM) / (256 * 8), 256>>>(x);
    transpose_w_kernel<<<dim3(32, 32), 256>>>(Wq, 0);
    transpose_w_kernel<<<dim3(32, 32), 256>>>(Wk, 1);
    transpose_w_kernel<<<dim3(32, 32), 256>>>(Wv, 2);
    qkv_kernel<<<dim3(DDIM / 128, N_TOK / 128, 3), 128>>>(bq, bk, bv);
    transpose_v_kernel<<<dim3(DDIM / 32, N_TOK / 32), 256>>>();
    score_kernel<<<dim3(N_TOK / 128, N_TOK / 128), 128>>>();
    rowsum_kernel<<<N_TOK, 256>>>();
    pv_kernel<<<dim3(DDIM / 128, N_TOK / 128), 128>>>(out);
}

// round 8
// speedup vs baseline: 2.9402x; 1.0994x over previous
#include <cuda_runtime.h>
#include <cuda_fp16.h>
#include <cstdint>

#define N_TOK 4096
#define DDIM  1024
#define BK 32            // halves per k-chunk (2 x k16 planes)
#define STAGE 16384      // A 8KB + B 8KB
#define NSTAGE 3         // 48KB static smem

// Scratch (device globals; no runtime allocation)
__device__ __half g_Xh[(size_t)N_TOK * DDIM];
__device__ __half g_Q[(size_t)N_TOK * DDIM];
__device__ __half g_K[(size_t)N_TOK * DDIM];
__device__ __half g_V[(size_t)N_TOK * DDIM];
__device__ __half g_Vt[(size_t)DDIM * N_TOK];     // V^T [dim][token]
__device__ __half g_Wt[3][(size_t)DDIM * DDIM];   // W^T [out][in]
__device__ __half g_P[(size_t)N_TOK * N_TOK];
__device__ float  g_rsum[N_TOK];

// Smem tile layout (per stage): A = 128 rows x 32 halves (64B/row) at 0,
// B = same at 8192. 16B chunk c of row r stored at r*64 + 16*(c ^ ((r>>1)&3)).
// Verified conflict-free for cp.async 16B stores and ldmatrix.x4 loads.

__device__ __forceinline__ void mma_f16(float d[4], uint32_t a0, uint32_t a1, uint32_t a2,
                                        uint32_t a3, uint32_t b0, uint32_t b1) {
    asm volatile(
        "mma.sync.aligned.m16n8k16.row.col.f32.f16.f16.f32 "
        "{%0,%1,%2,%3}, {%4,%5,%6,%7}, {%8,%9}, {%0,%1,%2,%3};\n"
        : "+f"(d[0]), "+f"(d[1]), "+f"(d[2]), "+f"(d[3])
        : "r"(a0), "r"(a1), "r"(a2), "r"(a3), "r"(b0), "r"(b1));
}
__device__ __forceinline__ void cp_async16(uint32_t s, const void* g) {
    asm volatile("cp.async.cg.shared.global [%0], [%1], 16;" :: "r"(s), "l"(g));
}
__device__ __forceinline__ void cp_commit() {
    asm volatile("cp.async.commit_group;" ::: "memory");
}
template <int N>
__device__ __forceinline__ void cp_wait() {
    asm volatile("cp.async.wait_group %0;" :: "n"(N) : "memory");
}
__device__ __forceinline__ void ldsm_x4(uint32_t* r, uint32_t addr) {
    asm volatile("ldmatrix.sync.aligned.m8n8.x4.shared.b16 {%0,%1,%2,%3}, [%4];"
        : "=r"(r[0]), "=r"(r[1]), "=r"(r[2]), "=r"(r[3]) : "r"(addr));
}

// Issue cp.async for one stage: 4 x 16B chunks each of A and B per thread (128 thr).
__device__ __forceinline__ void stage_load(
    uint32_t sbase, const __half* __restrict__ A, const __half* __restrict__ B,
    int lda, int ldb, int bm, int bn, int kt, int tid)
{
#pragma unroll
    for (int i = 0; i < 4; i++) {
        int chunk = tid + i * 128;
        int row = chunk >> 2, c = chunk & 3;
        uint32_t so = row * 64 + 16 * (c ^ ((row >> 1) & 3));
        cp_async16(sbase + so,        A + (size_t)(bm + row) * lda + kt * BK + c * 8);
        cp_async16(sbase + 8192 + so, B + (size_t)(bn + row) * ldb + kt * BK + c * 8);
    }
}

// CTA 128x128, 4 warps as 2(M) x 2(N), warp tile 64x64, 3-stage cp.async + ldmatrix.
// A [M x K] half row-major, B [N x K] half row-major, fp32 accum.
__device__ __forceinline__ void gemm_main(
    const __half* __restrict__ A, const __half* __restrict__ B,
    int lda, int ldb, int kIters, int bm, int bn,
    char* smem, float (&acc)[4][8][4])
{
    const int tid = threadIdx.x;
    const uint32_t sb = (uint32_t)__cvta_generic_to_shared(smem);

#pragma unroll
    for (int mi = 0; mi < 4; mi++)
#pragma unroll
        for (int ni = 0; ni < 8; ni++)
#pragma unroll
            for (int j = 0; j < 4; j++) acc[mi][ni][j] = 0.f;

    stage_load(sb,         A, B, lda, ldb, bm, bn, 0, tid);
    cp_commit();
    stage_load(sb + STAGE, A, B, lda, ldb, bm, bn, 1, tid);
    cp_commit();

    const int lane = tid & 31, w = tid >> 5;
    const int wm = (w & 1) * 64, wn = (w >> 1) * 64;
    const int rA = wm + (lane & 15), rB = wn + (lane & 15);
    const int cl = lane >> 4;
    uint32_t aAddr[2], bAddr[2];
#pragma unroll
    for (int h = 0; h < 2; h++) {
        aAddr[h] = rA * 64 + 16 * ((2 * h + cl) ^ ((rA >> 1) & 3));
        bAddr[h] = 8192 + rB * 64 + 16 * ((2 * h + cl) ^ ((rB >> 1) & 3));
    }

    for (int kt = 0; kt < kIters; ++kt) {
        cp_wait<1>();
        __syncthreads();
        const uint32_t sst = sb + (uint32_t)((kt % NSTAGE) * STAGE);

#pragma unroll
        for (int h = 0; h < 2; h++) {
            uint32_t a[4][4], bq[4][4];
#pragma unroll
            for (int mi = 0; mi < 4; mi++)
                ldsm_x4(a[mi], sst + aAddr[h] + mi * 1024);
#pragma unroll
            for (int nb = 0; nb < 4; nb++)
                ldsm_x4(bq[nb], sst + bAddr[h] + nb * 1024);
#pragma unroll
            for (int mi = 0; mi < 4; mi++)
#pragma unroll
                for (int ni = 0; ni < 8; ni++) {
                    const int nb = ni >> 1;
                    const uint32_t b0 = (ni & 1) ? bq[nb][1] : bq[nb][0];
                    const uint32_t b1 = (ni & 1) ? bq[nb][3] : bq[nb][2];
                    mma_f16(acc[mi][ni], a[mi][0], a[mi][1], a[mi][2], a[mi][3], b0, b1);
                }
        }

        if (kt + 2 < kIters)
            stage_load(sb + (uint32_t)(((kt + 2) % NSTAGE) * STAGE),
                       A, B, lda, ldb, bm, bn, kt + 2, tid);
        cp_commit();   // unconditional: keeps wait_group accounting aligned in the tail
    }
}

// ---------- x -> half ----------
__global__ void __launch_bounds__(256)
convert_x_kernel(const float* __restrict__ x)
{
    const size_t base = ((size_t)blockIdx.x * 256 + threadIdx.x) * 8;
    float4 v0 = *reinterpret_cast<const float4*>(x + base);
    float4 v1 = *reinterpret_cast<const float4*>(x + base + 4);
    __half2* o = reinterpret_cast<__half2*>(g_Xh + base);
    o[0] = __floats2half2_rn(v0.x, v0.y);
    o[1] = __floats2half2_rn(v0.z, v0.w);
    o[2] = __floats2half2_rn(v1.x, v1.y);
    o[3] = __floats2half2_rn(v1.z, v1.w);
}

// ---------- Wq/Wk/Wv (fp32 [in][out]) -> Wt half [out][in]; z selects ----------
__global__ void __launch_bounds__(256)
transpose_w_kernel(const float* __restrict__ wq, const float* __restrict__ wk,
                   const float* __restrict__ wv)
{
    __shared__ float t[32][33];
    const float* in = (blockIdx.z == 0) ? wq : (blockIdx.z == 1) ? wk : wv;
    __half* dst = g_Wt[blockIdx.z];
    const int bx = blockIdx.x * 32, by = blockIdx.y * 32;
    const int tx = threadIdx.x & 31, ty = threadIdx.x >> 5;
#pragma unroll
    for (int i = 0; i < 32; i += 8)
        t[ty + i][tx] = in[(size_t)(by + ty + i) * DDIM + bx + tx];
    __syncthreads();
#pragma unroll
    for (int i = 0; i < 32; i += 8)
        dst[(size_t)(bx + ty + i) * DDIM + by + tx] = __float2half(t[tx][ty + i]);
}

// ---------- V (half [tok][dim]) -> Vt half [dim][tok] ----------
__global__ void __launch_bounds__(256)
transpose_v_kernel()
{
    __shared__ float t[32][33];
    const int bx = blockIdx.x * 32, by = blockIdx.y * 32;
    const int tx = threadIdx.x & 31, ty = threadIdx.x >> 5;
#pragma unroll
    for (int i = 0; i < 32; i += 8)
        t[ty + i][tx] = __half2float(g_V[(size_t)(by + ty + i) * DDIM + bx + tx]);
    __syncthreads();
#pragma unroll
    for (int i = 0; i < 32; i += 8)
        g_Vt[(size_t)(bx + ty + i) * N_TOK + by + tx] = __float2half(t[tx][ty + i]);
}

// ---------- Kernel 1: Q/K/V = X @ W + b (half out) ----------
__global__ void __launch_bounds__(128, 2)
qkv_kernel(const float* __restrict__ bq, const float* __restrict__ bk,
           const float* __restrict__ bv)
{
    __shared__ __align__(16) char smem[NSTAGE * STAGE];
    const float* bias; __half* O;
    if (blockIdx.z == 0)      { bias = bq; O = g_Q; }
    else if (blockIdx.z == 1) { bias = bk; O = g_K; }
    else                      { bias = bv; O = g_V; }
    const __half* W = g_Wt[blockIdx.z];

    const int bm = blockIdx.y * 128, bn = blockIdx.x * 128;
    float acc[4][8][4];
    gemm_main(g_Xh, W, DDIM, DDIM, DDIM / BK, bm, bn, smem, acc);

    const int w = threadIdx.x >> 5, lane = threadIdx.x & 31;
    const int wm = (w & 1) * 64, wn = (w >> 1) * 64;
    const int gid = lane >> 2, tig = lane & 3;
#pragma unroll
    for (int mi = 0; mi < 4; mi++) {
        int r0 = bm + wm + mi * 16 + gid;
#pragma unroll
        for (int ni = 0; ni < 8; ni++) {
            int c = bn + wn + ni * 8 + 2 * tig;
            float b0 = bias[c], b1 = bias[c + 1];
            *reinterpret_cast<__half2*>(&O[(size_t)r0 * DDIM + c]) =
                __floats2half2_rn(acc[mi][ni][0] + b0, acc[mi][ni][1] + b1);
            *reinterpret_cast<__half2*>(&O[(size_t)(r0 + 8) * DDIM + c]) =
                __floats2half2_rn(acc[mi][ni][2] + b0, acc[mi][ni][3] + b1);
        }
    }
}

// ---------- Kernel 2: P = exp(tanh(Q @ K^T) / 32) (half out) ----------
__global__ void __launch_bounds__(128, 2)
score_kernel()
{
    __shared__ __align__(16) char smem[NSTAGE * STAGE];
    const int bm = blockIdx.y * 128, bn = blockIdx.x * 128;
    float acc[4][8][4];
    gemm_main(g_Q, g_K, DDIM, DDIM, DDIM / BK, bm, bn, smem, acc);

    const int w = threadIdx.x >> 5, lane = threadIdx.x & 31;
    const int wm = (w & 1) * 64, wn = (w >> 1) * 64;
    const int gid = lane >> 2, tig = lane & 3;
    const float sc = 0.03125f;  // 1/sqrt(1024)
#pragma unroll
    for (int mi = 0; mi < 4; mi++) {
        int r0 = bm + wm + mi * 16 + gid;
#pragma unroll
        for (int ni = 0; ni < 8; ni++) {
            int c = bn + wn + ni * 8 + 2 * tig;
            float e[4];
#pragma unroll
            for (int q = 0; q < 4; q++) {
                float t;
                asm("tanh.approx.f32 %0, %1;" : "=f"(t) : "f"(acc[mi][ni][q]));
                e[q] = __expf(t * sc);
            }
            *reinterpret_cast<__half2*>(&g_P[(size_t)r0 * N_TOK + c]) =
                __floats2half2_rn(e[0], e[1]);
            *reinterpret_cast<__half2*>(&g_P[(size_t)(r0 + 8) * N_TOK + c]) =
                __floats2half2_rn(e[2], e[3]);
        }
    }
}

// ---------- Kernel 3: row sums of P (half in, fp32 sum) ----------
__global__ void __launch_bounds__(256)
rowsum_kernel()
{
    const int row = blockIdx.x;
    const uint4* p = reinterpret_cast<const uint4*>(g_P + (size_t)row * N_TOK);
    float s = 0.f;
#pragma unroll
    for (int i = 0; i < 2; i++) {
        uint4 u = p[threadIdx.x + i * 256];
        float2 f0 = __half22float2(*reinterpret_cast<__half2*>(&u.x));
        float2 f1 = __half22float2(*reinterpret_cast<__half2*>(&u.y));
        float2 f2 = __half22float2(*reinterpret_cast<__half2*>(&u.z));
        float2 f3 = __half22float2(*reinterpret_cast<__half2*>(&u.w));
        s += (f0.x + f0.y) + (f1.x + f1.y) + (f2.x + f2.y) + (f3.x + f3.y);
    }
#pragma unroll
    for (int o = 16; o > 0; o >>= 1) s += __shfl_xor_sync(0xffffffffu, s, o);
    __shared__ float red[8];
    if ((threadIdx.x & 31) == 0) red[threadIdx.x >> 5] = s;
    __syncthreads();
    if (threadIdx.x < 8) {
        float t = red[threadIdx.x];
#pragma unroll
        for (int o = 4; o > 0; o >>= 1) t += __shfl_xor_sync(0xffu, t, o);
        if (threadIdx.x == 0) g_rsum[row] = t;
    }
}

// ---------- Kernel 4: out = (P @ V) / rsum (fp32 out) ----------
__global__ void __launch_bounds__(128, 2)
pv_kernel(float* __restrict__ out)
{
    __shared__ __align__(16) char smem[NSTAGE * STAGE];
    const int bm = blockIdx.y * 128, bn = blockIdx.x * 128;
    float acc[4][8][4];
    gemm_main(g_P, g_Vt, N_TOK, N_TOK, N_TOK / BK, bm, bn, smem, acc);

    const int w = threadIdx.x >> 5, lane = threadIdx.x & 31;
    const int wm = (w & 1) * 64, wn = (w >> 1) * 64;
    const int gid = lane >> 2, tig = lane & 3;
#pragma unroll
    for (int mi = 0; mi < 4; mi++) {
        int r0 = bm + wm + mi * 16 + gid;
        float inv0 = 1.0f / g_rsum[r0];
        float inv1 = 1.0f / g_rsum[r0 + 8];
#pragma unroll
        for (int ni = 0; ni < 8; ni++) {
            int c = bn + wn + ni * 8 + 2 * tig;
            float2 v0 = make_float2(acc[mi][ni][0] * inv0, acc[mi][ni][1] * inv0);
            float2 v1 = make_float2(acc[mi][ni][2] * inv1, acc[mi][ni][3] * inv1);
            *reinterpret_cast<float2*>(&out[(size_t)r0 * DDIM + c]) = v0;
            *reinterpret_cast<float2*>(&out[(size_t)(r0 + 8) * DDIM + c]) = v1;
        }
    }
}

extern "C" void kernel_launch(void* const* d_in, const int* in_sizes, int n_in,
                              void* d_out, int out_size)
{
    const float* x  = (const float*)d_in[0];
    const float* Wq = (const float*)d_in[1];
    const float* bq = (const float*)d_in[2];
    const float* Wk = (const float*)d_in[3];
    const float* bk = (const float*)d_in[4];
    const float* Wv = (const float*)d_in[5];
    const float* bv = (const float*)d_in[6];
    float* out = (float*)d_out;

    convert_x_kernel<<<(N_TOK * DDIM) / (256 * 8), 256>>>(x);
    transpose_w_kernel<<<dim3(32, 32, 3), 256>>>(Wq, Wk, Wv);
    qkv_kernel<<<dim3(DDIM / 128, N_TOK / 128, 3), 128>>>(bq, bk, bv);
    transpose_v_kernel<<<dim3(DDIM / 32, N_TOK / 32), 256>>>();
    score_kernel<<<dim3(N_TOK / 128, N_TOK / 128), 128>>>();
    rowsum_kernel<<<N_TOK, 256>>>();
    pv_kernel<<<dim3(DDIM / 128, N_TOK / 128), 128>>>(out);
}

// round 10
// speedup vs baseline: 3.2405x; 1.1022x over previous
#include <cuda_runtime.h>
#include <cuda_fp16.h>
#include <cstdint>

#define N_TOK 4096
#define DDIM  1024
#define BK 64                 // halves per k-chunk (4 x k16 planes)
#define STAGE 32768           // A 16KB + B 16KB
#define NSTAGE 3              // 96KB dynamic smem
#define SMEM_TOT (NSTAGE * STAGE)

// Scratch (device globals; no runtime allocation)
__device__ __half g_Xh[(size_t)N_TOK * DDIM];
__device__ __half g_Q[(size_t)N_TOK * DDIM];
__device__ __half g_K[(size_t)N_TOK * DDIM];
__device__ __half g_V[(size_t)N_TOK * DDIM];
__device__ __half g_Vt[(size_t)DDIM * N_TOK];     // V^T [dim][token]
__device__ __half g_Wt[3][(size_t)DDIM * DDIM];   // W^T [out][in]
__device__ __half g_P[(size_t)N_TOK * N_TOK];
__device__ float  g_rsum[N_TOK];

// Smem tile layout (per stage): A = 128 rows x 64 halves (128B/row) at 0, B at 16384.
// 16B chunk c (0..7) of row r stored at r*128 + 16*(c ^ (r & 7)).
// Conflict-free for cp.async 16B stores and ldmatrix.x4 8-lane rounds.

__device__ __forceinline__ void mma_f16(float d[4], uint32_t a0, uint32_t a1, uint32_t a2,
                                        uint32_t a3, uint32_t b0, uint32_t b1) {
    asm volatile(
        "mma.sync.aligned.m16n8k16.row.col.f32.f16.f16.f32 "
        "{%0,%1,%2,%3}, {%4,%5,%6,%7}, {%8,%9}, {%0,%1,%2,%3};\n"
        : "+f"(d[0]), "+f"(d[1]), "+f"(d[2]), "+f"(d[3])
        : "r"(a0), "r"(a1), "r"(a2), "r"(a3), "r"(b0), "r"(b1));
}
__device__ __forceinline__ void cp_async16(uint32_t s, const void* g) {
    asm volatile("cp.async.cg.shared.global [%0], [%1], 16;" :: "r"(s), "l"(g));
}
__device__ __forceinline__ void cp_commit() {
    asm volatile("cp.async.commit_group;" ::: "memory");
}
template <int N>
__device__ __forceinline__ void cp_wait() {
    asm volatile("cp.async.wait_group %0;" :: "n"(N) : "memory");
}
__device__ __forceinline__ void ldsm_x4(uint32_t* r, uint32_t addr) {
    asm volatile("ldmatrix.sync.aligned.m8n8.x4.shared.b16 {%0,%1,%2,%3}, [%4];"
        : "=r"(r[0]), "=r"(r[1]), "=r"(r[2]), "=r"(r[3]) : "r"(addr));
}

// Issue cp.async for one stage: 8 x 16B chunks each of A and B per thread (128 thr).
__device__ __forceinline__ void stage_load(
    uint32_t sbase, const __half* __restrict__ A, const __half* __restrict__ B,
    int lda, int ldb, int bm, int bn, int kt, int tid)
{
#pragma unroll
    for (int i = 0; i < 8; i++) {
        int chunk = tid + i * 128;
        int row = chunk >> 3, c = chunk & 7;
        uint32_t so = row * 128 + 16 * (c ^ (row & 7));
        cp_async16(sbase + so,         A + (size_t)(bm + row) * lda + kt * BK + c * 8);
        cp_async16(sbase + 16384 + so, B + (size_t)(bn + row) * ldb + kt * BK + c * 8);
    }
}

// CTA 128x128, 4 warps as 2(M) x 2(N), warp tile 64x64, 3-stage cp.async + ldmatrix.
// A [M x K] half row-major, B [N x K] half row-major, fp32 accum.
__device__ __forceinline__ void gemm_main(
    const __half* __restrict__ A, const __half* __restrict__ B,
    int lda, int ldb, int kIters, int bm, int bn,
    char* smem, float (&acc)[4][8][4])
{
    const int tid = threadIdx.x;
    const uint32_t sb = (uint32_t)__cvta_generic_to_shared(smem);

#pragma unroll
    for (int mi = 0; mi < 4; mi++)
#pragma unroll
        for (int ni = 0; ni < 8; ni++)
#pragma unroll
            for (int j = 0; j < 4; j++) acc[mi][ni][j] = 0.f;

    stage_load(sb,         A, B, lda, ldb, bm, bn, 0, tid);
    cp_commit();
    stage_load(sb + STAGE, A, B, lda, ldb, bm, bn, 1, tid);
    cp_commit();

    const int lane = tid & 31, w = tid >> 5;
    const int wm = (w & 1) * 64, wn = (w >> 1) * 64;
    const int rA = wm + (lane & 15), rB = wn + (lane & 15);
    const int cl = lane >> 4;
    uint32_t aAddr[4], bAddr[4];
#pragma unroll
    for (int h = 0; h < 4; h++) {
        aAddr[h] = rA * 128 + 16 * ((2 * h + cl) ^ (rA & 7));
        bAddr[h] = 16384 + rB * 128 + 16 * ((2 * h + cl) ^ (rB & 7));
    }

    for (int kt = 0; kt < kIters; ++kt) {
        cp_wait<1>();
        __syncthreads();
        const uint32_t sst = sb + (uint32_t)((kt % NSTAGE) * STAGE);

#pragma unroll
        for (int h = 0; h < 4; h++) {
            uint32_t a[4][4], bq[4][4];
#pragma unroll
            for (int mi = 0; mi < 4; mi++)
                ldsm_x4(a[mi], sst + aAddr[h] + mi * 2048);
#pragma unroll
            for (int nb = 0; nb < 4; nb++)
                ldsm_x4(bq[nb], sst + bAddr[h] + nb * 2048);
#pragma unroll
            for (int mi = 0; mi < 4; mi++)
#pragma unroll
                for (int ni = 0; ni < 8; ni++) {
                    const int nb = ni >> 1;
                    const uint32_t b0 = (ni & 1) ? bq[nb][1] : bq[nb][0];
                    const uint32_t b1 = (ni & 1) ? bq[nb][3] : bq[nb][2];
                    mma_f16(acc[mi][ni], a[mi][0], a[mi][1], a[mi][2], a[mi][3], b0, b1);
                }
        }

        if (kt + 2 < kIters)
            stage_load(sb + (uint32_t)(((kt + 2) % NSTAGE) * STAGE),
                       A, B, lda, ldb, bm, bn, kt + 2, tid);
        cp_commit();   // unconditional: keeps wait_group accounting aligned in the tail
    }
}

// ---------- x -> half; also zero g_rsum ----------
__global__ void __launch_bounds__(256)
convert_x_kernel(const float* __restrict__ x)
{
    if (blockIdx.x < 16) g_rsum[blockIdx.x * 256 + threadIdx.x] = 0.f;
    const size_t base = ((size_t)blockIdx.x * 256 + threadIdx.x) * 8;
    float4 v0 = *reinterpret_cast<const float4*>(x + base);
    float4 v1 = *reinterpret_cast<const float4*>(x + base + 4);
    __half2* o = reinterpret_cast<__half2*>(g_Xh + base);
    o[0] = __floats2half2_rn(v0.x, v0.y);
    o[1] = __floats2half2_rn(v0.z, v0.w);
    o[2] = __floats2half2_rn(v1.x, v1.y);
    o[3] = __floats2half2_rn(v1.z, v1.w);
}

// ---------- Wq/Wk/Wv (fp32 [in][out]) -> Wt half [out][in]; z selects ----------
__global__ void __launch_bounds__(256)
transpose_w_kernel(const float* __restrict__ wq, const float* __restrict__ wk,
                   const float* __restrict__ wv)
{
    __shared__ float t[32][33];
    const float* in = (blockIdx.z == 0) ? wq : (blockIdx.z == 1) ? wk : wv;
    __half* dst = g_Wt[blockIdx.z];
    const int bx = blockIdx.x * 32, by = blockIdx.y * 32;
    const int tx = threadIdx.x & 31, ty = threadIdx.x >> 5;
#pragma unroll
    for (int i = 0; i < 32; i += 8)
        t[ty + i][tx] = in[(size_t)(by + ty + i) * DDIM + bx + tx];
    __syncthreads();
#pragma unroll
    for (int i = 0; i < 32; i += 8)
        dst[(size_t)(bx + ty + i) * DDIM + by + tx] = __float2half(t[tx][ty + i]);
}

// ---------- V (half [tok][dim]) -> Vt half [dim][tok] ----------
__global__ void __launch_bounds__(256)
transpose_v_kernel()
{
    __shared__ float t[32][33];
    const int bx = blockIdx.x * 32, by = blockIdx.y * 32;
    const int tx = threadIdx.x & 31, ty = threadIdx.x >> 5;
#pragma unroll
    for (int i = 0; i < 32; i += 8)
        t[ty + i][tx] = __half2float(g_V[(size_t)(by + ty + i) * DDIM + bx + tx]);
    __syncthreads();
#pragma unroll
    for (int i = 0; i < 32; i += 8)
        g_Vt[(size_t)(bx + ty + i) * N_TOK + by + tx] = __float2half(t[tx][ty + i]);
}

// ---------- Kernel 1: Q/K/V = X @ W + b (half out) ----------
__global__ void __launch_bounds__(128, 2)
qkv_kernel(const float* __restrict__ bq, const float* __restrict__ bk,
           const float* __restrict__ bv)
{
    extern __shared__ __align__(16) char smem[];
    const float* bias; __half* O;
    if (blockIdx.z == 0)      { bias = bq; O = g_Q; }
    else if (blockIdx.z == 1) { bias = bk; O = g_K; }
    else                      { bias = bv; O = g_V; }
    const __half* W = g_Wt[blockIdx.z];

    const int bm = blockIdx.y * 128, bn = blockIdx.x * 128;
    float acc[4][8][4];
    gemm_main(g_Xh, W, DDIM, DDIM, DDIM / BK, bm, bn, smem, acc);

    const int w = threadIdx.x >> 5, lane = threadIdx.x & 31;
    const int wm = (w & 1) * 64, wn = (w >> 1) * 64;
    const int gid = lane >> 2, tig = lane & 3;
#pragma unroll
    for (int mi = 0; mi < 4; mi++) {
        int r0 = bm + wm + mi * 16 + gid;
#pragma unroll
        for (int ni = 0; ni < 8; ni++) {
            int c = bn + wn + ni * 8 + 2 * tig;
            float b0 = bias[c], b1 = bias[c + 1];
            *reinterpret_cast<__half2*>(&O[(size_t)r0 * DDIM + c]) =
                __floats2half2_rn(acc[mi][ni][0] + b0, acc[mi][ni][1] + b1);
            *reinterpret_cast<__half2*>(&O[(size_t)(r0 + 8) * DDIM + c]) =
                __floats2half2_rn(acc[mi][ni][2] + b0, acc[mi][ni][3] + b1);
        }
    }
}

// ---------- Kernel 2: P = exp(tanh(Q @ K^T)/32), fused row-sum atomics ----------
__global__ void __launch_bounds__(128, 2)
score_kernel()
{
    extern __shared__ __align__(16) char smem[];
    const int bm = blockIdx.y * 128, bn = blockIdx.x * 128;
    float acc[4][8][4];
    gemm_main(g_Q, g_K, DDIM, DDIM, DDIM / BK, bm, bn, smem, acc);

    const int w = threadIdx.x >> 5, lane = threadIdx.x & 31;
    const int wm = (w & 1) * 64, wn = (w >> 1) * 64;
    const int gid = lane >> 2, tig = lane & 3;
    const float sc = 0.03125f;  // 1/sqrt(1024)
#pragma unroll
    for (int mi = 0; mi < 4; mi++) {
        int r0 = bm + wm + mi * 16 + gid;
        float slo = 0.f, shi = 0.f;
#pragma unroll
        for (int ni = 0; ni < 8; ni++) {
            int c = bn + wn + ni * 8 + 2 * tig;
            float e[4];
#pragma unroll
            for (int q = 0; q < 4; q++) {
                float t;
                asm("tanh.approx.f32 %0, %1;" : "=f"(t) : "f"(acc[mi][ni][q]));
                e[q] = __expf(t * sc);
            }
            slo += e[0] + e[1];
            shi += e[2] + e[3];
            *reinterpret_cast<__half2*>(&g_P[(size_t)r0 * N_TOK + c]) =
                __floats2half2_rn(e[0], e[1]);
            *reinterpret_cast<__half2*>(&g_P[(size_t)(r0 + 8) * N_TOK + c]) =
                __floats2half2_rn(e[2], e[3]);
        }
        // quad-reduce over tig, then one atomic per row per warp
        slo += __shfl_xor_sync(0xffffffffu, slo, 1);
        slo += __shfl_xor_sync(0xffffffffu, slo, 2);
        shi += __shfl_xor_sync(0xffffffffu, shi, 1);
        shi += __shfl_xor_sync(0xffffffffu, shi, 2);
        if (tig == 0) {
            atomicAdd(&g_rsum[r0], slo);
            atomicAdd(&g_rsum[r0 + 8], shi);
        }
    }
}

// ---------- Kernel 3: out = (P @ V) / rsum (fp32 out) ----------
__global__ void __launch_bounds__(128, 2)
pv_kernel(float* __restrict__ out)
{
    extern __shared__ __align__(16) char smem[];
    const int bm = blockIdx.y * 128, bn = blockIdx.x * 128;
    float acc[4][8][4];
    gemm_main(g_P, g_Vt, N_TOK, N_TOK, N_TOK / BK, bm, bn, smem, acc);

    const int w = threadIdx.x >> 5, lane = threadIdx.x & 31;
    const int wm = (w & 1) * 64, wn = (w >> 1) * 64;
    const int gid = lane >> 2, tig = lane & 3;
#pragma unroll
    for (int mi = 0; mi < 4; mi++) {
        int r0 = bm + wm + mi * 16 + gid;
        float inv0 = 1.0f / g_rsum[r0];
        float inv1 = 1.0f / g_rsum[r0 + 8];
#pragma unroll
        for (int ni = 0; ni < 8; ni++) {
            int c = bn + wn + ni * 8 + 2 * tig;
            float2 v0 = make_float2(acc[mi][ni][0] * inv0, acc[mi][ni][1] * inv0);
            float2 v1 = make_float2(acc[mi][ni][2] * inv1, acc[mi][ni][3] * inv1);
            *reinterpret_cast<float2*>(&out[(size_t)r0 * DDIM + c]) = v0;
            *reinterpret_cast<float2*>(&out[(size_t)(r0 + 8) * DDIM + c]) = v1;
        }
    }
}

extern "C" void kernel_launch(void* const* d_in, const int* in_sizes, int n_in,
                              void* d_out, int out_size)
{
    const float* x  = (const float*)d_in[0];
    const float* Wq = (const float*)d_in[1];
    const float* bq = (const float*)d_in[2];
    const float* Wk = (const float*)d_in[3];
    const float* bk = (const float*)d_in[4];
    const float* Wv = (const float*)d_in[5];
    const float* bv = (const float*)d_in[6];
    float* out = (float*)d_out;

    cudaFuncSetAttribute(qkv_kernel,   cudaFuncAttributeMaxDynamicSharedMemorySize, SMEM_TOT);
    cudaFuncSetAttribute(score_kernel, cudaFuncAttributeMaxDynamicSharedMemorySize, SMEM_TOT);
    cudaFuncSetAttribute(pv_kernel,    cudaFuncAttributeMaxDynamicSharedMemorySize, SMEM_TOT);

    convert_x_kernel<<<(N_TOK * DDIM) / (256 * 8), 256>>>(x);
    transpose_w_kernel<<<dim3(32, 32, 3), 256>>>(Wq, Wk, Wv);
    qkv_kernel<<<dim3(DDIM / 128, N_TOK / 128, 3), 128, SMEM_TOT>>>(bq, bk, bv);
    transpose_v_kernel<<<dim3(DDIM / 32, N_TOK / 32), 256>>>();
    score_kernel<<<dim3(N_TOK / 128, N_TOK / 128), 128, SMEM_TOT>>>();
    pv_kernel<<<dim3(DDIM / 128, N_TOK / 128), 128, SMEM_TOT>>>(out);
}

// round 11
// speedup vs baseline: 3.3006x; 1.0185x over previous
#include <cuda_runtime.h>
#include <cuda_fp16.h>
#include <cstdint>

#define N_TOK 4096
#define DDIM  1024
#define BK 64                 // halves per k-chunk (4 x k16 planes)
#define STAGE 32768           // A 16KB + B 16KB
#define NSTAGE 3              // 96KB dynamic smem
#define SMEM_TOT (NSTAGE * STAGE)

// Scratch (device globals; no runtime allocation)
__device__ __half g_Xh[(size_t)N_TOK * DDIM];
__device__ __half g_Q[(size_t)N_TOK * DDIM];
__device__ __half g_K[(size_t)N_TOK * DDIM];
__device__ __half g_Vt[(size_t)DDIM * N_TOK];     // V^T [dim][token]
__device__ __half g_Wt[3][(size_t)DDIM * DDIM];   // W^T [out][in]
__device__ __half g_P[(size_t)N_TOK * N_TOK];
__device__ float  g_rsum[N_TOK];

// Smem tile layout (per stage): A = 128 rows x 64 halves (128B/row) at 0, B at 16384.
// 16B chunk c (0..7) of row r stored at r*128 + 16*(c ^ (r & 7)).
// Conflict-free for cp.async 16B stores and ldmatrix.x4 8-lane rounds.

__device__ __forceinline__ void mma_f16(float d[4], uint32_t a0, uint32_t a1, uint32_t a2,
                                        uint32_t a3, uint32_t b0, uint32_t b1) {
    asm volatile(
        "mma.sync.aligned.m16n8k16.row.col.f32.f16.f16.f32 "
        "{%0,%1,%2,%3}, {%4,%5,%6,%7}, {%8,%9}, {%0,%1,%2,%3};\n"
        : "+f"(d[0]), "+f"(d[1]), "+f"(d[2]), "+f"(d[3])
        : "r"(a0), "r"(a1), "r"(a2), "r"(a3), "r"(b0), "r"(b1));
}
__device__ __forceinline__ void cp_async16(uint32_t s, const void* g) {
    asm volatile("cp.async.cg.shared.global [%0], [%1], 16;" :: "r"(s), "l"(g));
}
__device__ __forceinline__ void cp_commit() {
    asm volatile("cp.async.commit_group;" ::: "memory");
}
template <int N>
__device__ __forceinline__ void cp_wait() {
    asm volatile("cp.async.wait_group %0;" :: "n"(N) : "memory");
}
__device__ __forceinline__ void ldsm_x4(uint32_t* r, uint32_t addr) {
    asm volatile("ldmatrix.sync.aligned.m8n8.x4.shared.b16 {%0,%1,%2,%3}, [%4];"
        : "=r"(r[0]), "=r"(r[1]), "=r"(r[2]), "=r"(r[3]) : "r"(addr));
}

// Issue cp.async for one stage: 8 x 16B chunks each of A and B per thread (128 thr).
__device__ __forceinline__ void stage_load(
    uint32_t sbase, const __half* __restrict__ A, const __half* __restrict__ B,
    int lda, int ldb, int bm, int bn, int kt, int tid)
{
#pragma unroll
    for (int i = 0; i < 8; i++) {
        int chunk = tid + i * 128;
        int row = chunk >> 3, c = chunk & 7;
        uint32_t so = row * 128 + 16 * (c ^ (row & 7));
        cp_async16(sbase + so,         A + (size_t)(bm + row) * lda + kt * BK + c * 8);
        cp_async16(sbase + 16384 + so, B + (size_t)(bn + row) * ldb + kt * BK + c * 8);
    }
}

// CTA 128x128, 4 warps as 2(M) x 2(N), warp tile 64x64, 3-stage cp.async + ldmatrix.
// A [M x K] half row-major, B [N x K] half row-major, fp32 accum.
__device__ __forceinline__ void gemm_main(
    const __half* __restrict__ A, const __half* __restrict__ B,
    int lda, int ldb, int kIters, int bm, int bn,
    char* smem, float (&acc)[4][8][4])
{
    const int tid = threadIdx.x;
    const uint32_t sb = (uint32_t)__cvta_generic_to_shared(smem);

#pragma unroll
    for (int mi = 0; mi < 4; mi++)
#pragma unroll
        for (int ni = 0; ni < 8; ni++)
#pragma unroll
            for (int j = 0; j < 4; j++) acc[mi][ni][j] = 0.f;

    stage_load(sb,         A, B, lda, ldb, bm, bn, 0, tid);
    cp_commit();
    stage_load(sb + STAGE, A, B, lda, ldb, bm, bn, 1, tid);
    cp_commit();

    const int lane = tid & 31, w = tid >> 5;
    const int wm = (w & 1) * 64, wn = (w >> 1) * 64;
    const int rA = wm + (lane & 15), rB = wn + (lane & 15);
    const int cl = lane >> 4;
    uint32_t aAddr[4], bAddr[4];
#pragma unroll
    for (int h = 0; h < 4; h++) {
        aAddr[h] = rA * 128 + 16 * ((2 * h + cl) ^ (rA & 7));
        bAddr[h] = 16384 + rB * 128 + 16 * ((2 * h + cl) ^ (rB & 7));
    }

    for (int kt = 0; kt < kIters; ++kt) {
        cp_wait<1>();
        __syncthreads();
        const uint32_t sst = sb + (uint32_t)((kt % NSTAGE) * STAGE);

        // Prefetch stage kt+2 BEFORE compute: sync above proves stage (kt+2)%3
        // (== (kt-1)%3) is fully consumed, and issuing now overlaps the LDGSTS
        // stream with the 128-MMA body below.
        if (kt + 2 < kIters)
            stage_load(sb + (uint32_t)(((kt + 2) % NSTAGE) * STAGE),
                       A, B, lda, ldb, bm, bn, kt + 2, tid);
        cp_commit();   // unconditional: keeps wait_group accounting aligned in the tail

#pragma unroll
        for (int h = 0; h < 4; h++) {
            uint32_t a[4][4], bq[4][4];
#pragma unroll
            for (int mi = 0; mi < 4; mi++)
                ldsm_x4(a[mi], sst + aAddr[h] + mi * 2048);
#pragma unroll
            for (int nb = 0; nb < 4; nb++)
                ldsm_x4(bq[nb], sst + bAddr[h] + nb * 2048);
#pragma unroll
            for (int mi = 0; mi < 4; mi++)
#pragma unroll
                for (int ni = 0; ni < 8; ni++) {
                    const int nb = ni >> 1;
                    const uint32_t b0 = (ni & 1) ? bq[nb][1] : bq[nb][0];
                    const uint32_t b1 = (ni & 1) ? bq[nb][3] : bq[nb][2];
                    mma_f16(acc[mi][ni], a[mi][0], a[mi][1], a[mi][2], a[mi][3], b0, b1);
                }
        }
    }
}

// ---------- prep: x->half, W transposes, rsum zero (one launch) ----------
// blocks [0, 2048): convert x. blocks [2048, 5120): transpose Wq/Wk/Wv.
__global__ void __launch_bounds__(256)
prep_kernel(const float* __restrict__ x, const float* __restrict__ wq,
            const float* __restrict__ wk, const float* __restrict__ wv)
{
    __shared__ float t[32][33];
    const int b = blockIdx.x;
    if (b < 2048) {
        if (b < 16) g_rsum[b * 256 + threadIdx.x] = 0.f;
        const size_t base = ((size_t)b * 256 + threadIdx.x) * 8;
        float4 v0 = *reinterpret_cast<const float4*>(x + base);
        float4 v1 = *reinterpret_cast<const float4*>(x + base + 4);
        __half2* o = reinterpret_cast<__half2*>(g_Xh + base);
        o[0] = __floats2half2_rn(v0.x, v0.y);
        o[1] = __floats2half2_rn(v0.z, v0.w);
        o[2] = __floats2half2_rn(v1.x, v1.y);
        o[3] = __floats2half2_rn(v1.z, v1.w);
    } else {
        const int i = b - 2048;
        const int z = i >> 10, rem = i & 1023;
        const float* in = (z == 0) ? wq : (z == 1) ? wk : wv;
        __half* dst = g_Wt[z];
        const int bx = (rem & 31) * 32, by = (rem >> 5) * 32;
        const int tx = threadIdx.x & 31, ty = threadIdx.x >> 5;
#pragma unroll
        for (int i2 = 0; i2 < 32; i2 += 8)
            t[ty + i2][tx] = in[(size_t)(by + ty + i2) * DDIM + bx + tx];
        __syncthreads();
#pragma unroll
        for (int i2 = 0; i2 < 32; i2 += 8)
            dst[(size_t)(bx + ty + i2) * DDIM + by + tx] = __float2half(t[tx][ty + i2]);
    }
}

// ---------- Kernel 1: Q/K = X @ W + b ; z=2 computes Vt = Wv^T X^T + bv directly ----------
__global__ void __launch_bounds__(128, 2)
qkv_kernel(const float* __restrict__ bq, const float* __restrict__ bk,
           const float* __restrict__ bv)
{
    extern __shared__ __align__(16) char smem[];
    const int z = blockIdx.z;
    const __half* A; const __half* B; const float* bias; __half* O;
    int bm, bn, ldc;
    if (z < 2) {
        A = g_Xh; B = g_Wt[z]; O = (z == 0) ? g_Q : g_K;
        bias = (z == 0) ? bq : bk;
        bm = blockIdx.y * 128; bn = blockIdx.x * 128; ldc = DDIM;
    } else {
        // Vt[d][t] = sum_k Wt[2][d][k] * Xh[t][k] + bv[d]
        A = g_Wt[2]; B = g_Xh; O = g_Vt; bias = bv;
        bm = blockIdx.x * 128; bn = blockIdx.y * 128; ldc = N_TOK;
    }

    float acc[4][8][4];
    gemm_main(A, B, DDIM, DDIM, DDIM / BK, bm, bn, smem, acc);

    const int w = threadIdx.x >> 5, lane = threadIdx.x & 31;
    const int wm = (w & 1) * 64, wn = (w >> 1) * 64;
    const int gid = lane >> 2, tig = lane & 3;
#pragma unroll
    for (int mi = 0; mi < 4; mi++) {
        int r0 = bm + wm + mi * 16 + gid;
#pragma unroll
        for (int ni = 0; ni < 8; ni++) {
            int c = bn + wn + ni * 8 + 2 * tig;
            float b0, b1, b2, b3;
            if (z < 2) { b0 = bias[c]; b1 = bias[c + 1]; b2 = b0; b3 = b1; }
            else       { b0 = b1 = bias[r0]; b2 = b3 = bias[r0 + 8]; }
            *reinterpret_cast<__half2*>(&O[(size_t)r0 * ldc + c]) =
                __floats2half2_rn(acc[mi][ni][0] + b0, acc[mi][ni][1] + b1);
            *reinterpret_cast<__half2*>(&O[(size_t)(r0 + 8) * ldc + c]) =
                __floats2half2_rn(acc[mi][ni][2] + b2, acc[mi][ni][3] + b3);
        }
    }
}

// ---------- Kernel 2: P = exp(tanh(Q @ K^T)/32), fused row-sum atomics ----------
__global__ void __launch_bounds__(128, 2)
score_kernel()
{
    extern __shared__ __align__(16) char smem[];
    const int bm = blockIdx.y * 128, bn = blockIdx.x * 128;
    float acc[4][8][4];
    gemm_main(g_Q, g_K, DDIM, DDIM, DDIM / BK, bm, bn, smem, acc);

    const int w = threadIdx.x >> 5, lane = threadIdx.x & 31;
    const int wm = (w & 1) * 64, wn = (w >> 1) * 64;
    const int gid = lane >> 2, tig = lane & 3;
    const float sc = 0.03125f;  // 1/sqrt(1024)
#pragma unroll
    for (int mi = 0; mi < 4; mi++) {
        int r0 = bm + wm + mi * 16 + gid;
        float slo = 0.f, shi = 0.f;
#pragma unroll
        for (int ni = 0; ni < 8; ni++) {
            int c = bn + wn + ni * 8 + 2 * tig;
            float e[4];
#pragma unroll
            for (int q = 0; q < 4; q++) {
                float t;
                asm("tanh.approx.f32 %0, %1;" : "=f"(t) : "f"(acc[mi][ni][q]));
                e[q] = __expf(t * sc);
            }
            slo += e[0] + e[1];
            shi += e[2] + e[3];
            *reinterpret_cast<__half2*>(&g_P[(size_t)r0 * N_TOK + c]) =
                __floats2half2_rn(e[0], e[1]);
            *reinterpret_cast<__half2*>(&g_P[(size_t)(r0 + 8) * N_TOK + c]) =
                __floats2half2_rn(e[2], e[3]);
        }
        slo += __shfl_xor_sync(0xffffffffu, slo, 1);
        slo += __shfl_xor_sync(0xffffffffu, slo, 2);
        shi += __shfl_xor_sync(0xffffffffu, shi, 1);
        shi += __shfl_xor_sync(0xffffffffu, shi, 2);
        if (tig == 0) {
            atomicAdd(&g_rsum[r0], slo);
            atomicAdd(&g_rsum[r0 + 8], shi);
        }
    }
}

// ---------- Kernel 3: out = (P @ V) / rsum (fp32 out) ----------
__global__ void __launch_bounds__(128, 2)
pv_kernel(float* __restrict__ out)
{
    extern __shared__ __align__(16) char smem[];
    const int bm = blockIdx.y * 128, bn = blockIdx.x * 128;
    float acc[4][8][4];
    gemm_main(g_P, g_Vt, N_TOK, N_TOK, N_TOK / BK, bm, bn, smem, acc);

    const int w = threadIdx.x >> 5, lane = threadIdx.x & 31;
    const int wm = (w & 1) * 64, wn = (w >> 1) * 64;
    const int gid = lane >> 2, tig = lane & 3;
#pragma unroll
    for (int mi = 0; mi < 4; mi++) {
        int r0 = bm + wm + mi * 16 + gid;
        float inv0 = 1.0f / g_rsum[r0];
        float inv1 = 1.0f / g_rsum[r0 + 8];
#pragma unroll
        for (int ni = 0; ni < 8; ni++) {
            int c = bn + wn + ni * 8 + 2 * tig;
            float2 v0 = make_float2(acc[mi][ni][0] * inv0, acc[mi][ni][1] * inv0);
            float2 v1 = make_float2(acc[mi][ni][2] * inv1, acc[mi][ni][3] * inv1);
            *reinterpret_cast<float2*>(&out[(size_t)r0 * DDIM + c]) = v0;
            *reinterpret_cast<float2*>(&out[(size_t)(r0 + 8) * DDIM + c]) = v1;
        }
    }
}

extern "C" void kernel_launch(void* const* d_in, const int* in_sizes, int n_in,
                              void* d_out, int out_size)
{
    const float* x  = (const float*)d_in[0];
    const float* Wq = (const float*)d_in[1];
    const float* bq = (const float*)d_in[2];
    const float* Wk = (const float*)d_in[3];
    const float* bk = (const float*)d_in[4];
    const float* Wv = (const float*)d_in[5];
    const float* bv = (const float*)d_in[6];
    float* out = (float*)d_out;

    cudaFuncSetAttribute(qkv_kernel,   cudaFuncAttributeMaxDynamicSharedMemorySize, SMEM_TOT);
    cudaFuncSetAttribute(score_kernel, cudaFuncAttributeMaxDynamicSharedMemorySize, SMEM_TOT);
    cudaFuncSetAttribute(pv_kernel,    cudaFuncAttributeMaxDynamicSharedMemorySize, SMEM_TOT);

    prep_kernel<<<5120, 256>>>(x, Wq, Wk, Wv);
    qkv_kernel<<<dim3(DDIM / 128, N_TOK / 128, 3), 128, SMEM_TOT>>>(bq, bk, bv);
    score_kernel<<<dim3(N_TOK / 128, N_TOK / 128), 128, SMEM_TOT>>>();
    pv_kernel<<<dim3(DDIM / 128, N_TOK / 128), 128, SMEM_TOT>>>(out);
}